// round 1
// baseline (speedup 1.0000x reference)
#include <cuda_runtime.h>
#include <math.h>

// Problem shape (fixed by the reference's setup_inputs)
#define Bn 4
#define Tn 8192
#define Dn 1024
#define D4n (Dn / 4)   // 256 float4 groups across channel dim
#define Ln 64          // chunk length along time
#define Cn (Tn / Ln)   // 128 chunks

// Scratch: chunk-end states and chunk carry-in states, complex fp32.
// Layout: [c][b][k][d4] with k = sub-lane within the float4 group.
// 128*4*4*256 float2 = 4 MB each.
__device__ float2 g_ends [Cn * Bn * 4 * D4n];
__device__ float2 g_carry[Cn * Bn * 4 * D4n];

// ---------------------------------------------------------------------------
// pass1: local recurrence per chunk, zero initial state; emit chunk-end z.
// ---------------------------------------------------------------------------
__global__ __launch_bounds__(256)
void k_pass1(const float4* __restrict__ x,
             const float4* __restrict__ decay4,
             const float4* __restrict__ freq4)
{
    int tid = blockIdx.x * blockDim.x + threadIdx.x;
    if (tid >= Cn * Bn * D4n) return;
    int d4 = tid % D4n;
    int b  = (tid / D4n) % Bn;
    int c  = tid / (D4n * Bn);

    float4 a4 = decay4[d4];
    float4 f4 = freq4[d4];
    float av[4] = {a4.x, a4.y, a4.z, a4.w};
    float fv[4] = {f4.x, f4.y, f4.z, f4.w};

    float rre[4], rim[4], zre[4], zim[4];
#pragma unroll
    for (int k = 0; k < 4; k++) {
        float g = expf(-fabsf(av[k]));
        float s, co;
        sincosf(fv[k], &s, &co);
        rre[k] = g * co;
        rim[k] = g * s;
        zre[k] = 0.0f;
        zim[k] = 0.0f;
    }

    const float4* xp = x + (size_t)(b * Tn + c * Ln) * D4n + d4;
#pragma unroll 4
    for (int j = 0; j < Ln; j++) {
        float4 xv = xp[(size_t)j * D4n];
        float xr[4] = {xv.x, xv.y, xv.z, xv.w};
#pragma unroll
        for (int k = 0; k < 4; k++) {
            float nre = fmaf(rre[k], zre[k], fmaf(-rim[k], zim[k], xr[k]));
            float nim = fmaf(rre[k], zim[k], rim[k] * zre[k]);
            zre[k] = nre;
            zim[k] = nim;
        }
    }

#pragma unroll
    for (int k = 0; k < 4; k++)
        g_ends[((c * Bn + b) * 4 + k) * D4n + d4] = make_float2(zre[k], zim[k]);
}

// ---------------------------------------------------------------------------
// pass2: cross-chunk scan per (b,d). Multiplier r^L computed in closed form
// (double) so there is no accumulated rounding in the long-range factor.
// Writes carry-in (state at chunk start) for every chunk.
// ---------------------------------------------------------------------------
__global__ __launch_bounds__(256)
void k_pass2(const float* __restrict__ decay,
             const float* __restrict__ freq)
{
    int tid = blockIdx.x * blockDim.x + threadIdx.x;
    if (tid >= Bn * 4 * D4n) return;
    int d4 = tid % D4n;
    int k  = (tid / D4n) % 4;
    int b  = tid / (D4n * 4);
    int d  = 4 * d4 + k;

    double a  = fabs((double)decay[d]);
    double f  = (double)freq[d];
    double gl = exp(-a * (double)Ln);
    float rLre = (float)(gl * cos(f * (double)Ln));
    float rLim = (float)(gl * sin(f * (double)Ln));

    float cre = 0.0f, cim = 0.0f;
#pragma unroll 4
    for (int c = 0; c < Cn; c++) {
        int idx = ((c * Bn + b) * 4 + k) * D4n + d4;
        g_carry[idx] = make_float2(cre, cim);
        float2 e = g_ends[idx];
        float nre = fmaf(rLre, cre, fmaf(-rLim, cim, e.x));
        float nim = fmaf(rLre, cim, fmaf(rLim, cre, e.y));
        cre = nre;
        cim = nim;
    }
}

// ---------------------------------------------------------------------------
// pass3: rerun local recurrence seeded with carry-in; write y = Re(z).
// ---------------------------------------------------------------------------
__global__ __launch_bounds__(256)
void k_pass3(const float4* __restrict__ x,
             const float4* __restrict__ decay4,
             const float4* __restrict__ freq4,
             float4* __restrict__ y)
{
    int tid = blockIdx.x * blockDim.x + threadIdx.x;
    if (tid >= Cn * Bn * D4n) return;
    int d4 = tid % D4n;
    int b  = (tid / D4n) % Bn;
    int c  = tid / (D4n * Bn);

    float4 a4 = decay4[d4];
    float4 f4 = freq4[d4];
    float av[4] = {a4.x, a4.y, a4.z, a4.w};
    float fv[4] = {f4.x, f4.y, f4.z, f4.w};

    float rre[4], rim[4], zre[4], zim[4];
#pragma unroll
    for (int k = 0; k < 4; k++) {
        float g = expf(-fabsf(av[k]));
        float s, co;
        sincosf(fv[k], &s, &co);
        rre[k] = g * co;
        rim[k] = g * s;
        float2 cc = g_carry[((c * Bn + b) * 4 + k) * D4n + d4];
        zre[k] = cc.x;
        zim[k] = cc.y;
    }

    const float4* xp = x + (size_t)(b * Tn + c * Ln) * D4n + d4;
    float4*       yp = y + (size_t)(b * Tn + c * Ln) * D4n + d4;
#pragma unroll 4
    for (int j = 0; j < Ln; j++) {
        float4 xv = xp[(size_t)j * D4n];
        float xr[4] = {xv.x, xv.y, xv.z, xv.w};
#pragma unroll
        for (int k = 0; k < 4; k++) {
            float nre = fmaf(rre[k], zre[k], fmaf(-rim[k], zim[k], xr[k]));
            float nim = fmaf(rre[k], zim[k], rim[k] * zre[k]);
            zre[k] = nre;
            zim[k] = nim;
        }
        yp[(size_t)j * D4n] = make_float4(zre[0], zre[1], zre[2], zre[3]);
    }
}

// ---------------------------------------------------------------------------
extern "C" void kernel_launch(void* const* d_in, const int* in_sizes, int n_in,
                              void* d_out, int out_size)
{
    const float* x     = (const float*)d_in[0];
    const float* decay = (const float*)d_in[1];
    const float* freq  = (const float*)d_in[2];
    float* y = (float*)d_out;

    const int n1 = Cn * Bn * D4n;      // 131072 threads
    const int n2 = Bn * 4 * D4n;       // 4096 threads

    k_pass1<<<(n1 + 255) / 256, 256>>>((const float4*)x,
                                       (const float4*)decay,
                                       (const float4*)freq);
    k_pass2<<<(n2 + 255) / 256, 256>>>(decay, freq);
    k_pass3<<<(n1 + 255) / 256, 256>>>((const float4*)x,
                                       (const float4*)decay,
                                       (const float4*)freq,
                                       (float4*)y);
}

// round 2
// speedup vs baseline: 1.0629x; 1.0629x over previous
#include <cuda_runtime.h>
#include <math.h>

// Problem shape (fixed by the reference's setup_inputs)
#define Bn 4
#define Tn 8192
#define Dn 1024
#define D4n (Dn / 4)   // 256 float4 groups across channel dim
#define Ln 32          // chunk length along time (smaller -> more parallelism)
#define Cn (Tn / Ln)   // 256 chunks

// Per-channel recurrence multiplier r = exp(-|a|) * (cos f + i sin f),
// precomputed once. Stored as float2 per d.
__device__ float2 g_r[Dn];

// Scratch: chunk-end states and chunk carry-in states, complex fp32.
// Layout: [c][b][k][d4], k = sub-lane within the float4 group. 8 MB each.
__device__ float2 g_ends [Cn * Bn * 4 * D4n];
__device__ float2 g_carry[Cn * Bn * 4 * D4n];

// ---------------------------------------------------------------------------
// setup: compute r per channel (runs once per launch; trivial cost)
// ---------------------------------------------------------------------------
__global__ void k_setup(const float* __restrict__ decay,
                        const float* __restrict__ freq)
{
    int d = blockIdx.x * blockDim.x + threadIdx.x;
    if (d >= Dn) return;
    float g = expf(-fabsf(decay[d]));
    float s, co;
    sincosf(freq[d], &s, &co);
    g_r[d] = make_float2(g * co, g * s);
}

// ---------------------------------------------------------------------------
// pass1: local recurrence per chunk, zero initial state; emit chunk-end z.
// ---------------------------------------------------------------------------
__global__ __launch_bounds__(256)
void k_pass1(const float4* __restrict__ x)
{
    int tid = blockIdx.x * blockDim.x + threadIdx.x;
    int d4 = tid % D4n;
    int b  = (tid / D4n) % Bn;
    int c  = tid / (D4n * Bn);

    const float4* rp = (const float4*)g_r;   // g_r as float4 pairs: 2 float2 per float4
    float4 r01 = rp[2 * d4 + 0];             // (re0, im0, re1, im1)
    float4 r23 = rp[2 * d4 + 1];
    float rre[4] = {r01.x, r01.z, r23.x, r23.z};
    float rim[4] = {r01.y, r01.w, r23.y, r23.w};
    float zre[4] = {0.f, 0.f, 0.f, 0.f};
    float zim[4] = {0.f, 0.f, 0.f, 0.f};

    const float4* xp = x + (size_t)(b * Tn + c * Ln) * D4n + d4;
#pragma unroll 8
    for (int j = 0; j < Ln; j++) {
        float4 xv = xp[(size_t)j * D4n];
        float xr[4] = {xv.x, xv.y, xv.z, xv.w};
#pragma unroll
        for (int k = 0; k < 4; k++) {
            float nre = fmaf(rre[k], zre[k], fmaf(-rim[k], zim[k], xr[k]));
            float nim = fmaf(rre[k], zim[k], rim[k] * zre[k]);
            zre[k] = nre;
            zim[k] = nim;
        }
    }

#pragma unroll
    for (int k = 0; k < 4; k++)
        g_ends[((c * Bn + b) * 4 + k) * D4n + d4] = make_float2(zre[k], zim[k]);
}

// ---------------------------------------------------------------------------
// pass2: cross-chunk scan per (b,d). Multiplier r^L from the closed form in
// double precision, so no error accumulation in the long-range factor.
// ---------------------------------------------------------------------------
__global__ __launch_bounds__(256)
void k_pass2(const float* __restrict__ decay,
             const float* __restrict__ freq)
{
    int tid = blockIdx.x * blockDim.x + threadIdx.x;
    if (tid >= Bn * 4 * D4n) return;
    int d4 = tid % D4n;
    int k  = (tid / D4n) % 4;
    int b  = tid / (D4n * 4);
    int d  = 4 * d4 + k;

    double a  = fabs((double)decay[d]);
    double f  = (double)freq[d];
    double gl = exp(-a * (double)Ln);
    float rLre = (float)(gl * cos(f * (double)Ln));
    float rLim = (float)(gl * sin(f * (double)Ln));

    float cre = 0.0f, cim = 0.0f;
#pragma unroll 8
    for (int c = 0; c < Cn; c++) {
        int idx = ((c * Bn + b) * 4 + k) * D4n + d4;
        g_carry[idx] = make_float2(cre, cim);
        float2 e = g_ends[idx];
        float nre = fmaf(rLre, cre, fmaf(-rLim, cim, e.x));
        float nim = fmaf(rLre, cim, fmaf(rLim, cre, e.y));
        cre = nre;
        cim = nim;
    }
}

// ---------------------------------------------------------------------------
// pass3: rerun local recurrence seeded with carry-in; write y = Re(z).
// ---------------------------------------------------------------------------
__global__ __launch_bounds__(256)
void k_pass3(const float4* __restrict__ x,
             float4* __restrict__ y)
{
    int tid = blockIdx.x * blockDim.x + threadIdx.x;
    int d4 = tid % D4n;
    int b  = (tid / D4n) % Bn;
    int c  = tid / (D4n * Bn);

    const float4* rp = (const float4*)g_r;
    float4 r01 = rp[2 * d4 + 0];
    float4 r23 = rp[2 * d4 + 1];
    float rre[4] = {r01.x, r01.z, r23.x, r23.z};
    float rim[4] = {r01.y, r01.w, r23.y, r23.w};

    float zre[4], zim[4];
#pragma unroll
    for (int k = 0; k < 4; k++) {
        float2 cc = g_carry[((c * Bn + b) * 4 + k) * D4n + d4];
        zre[k] = cc.x;
        zim[k] = cc.y;
    }

    const float4* xp = x + (size_t)(b * Tn + c * Ln) * D4n + d4;
    float4*       yp = y + (size_t)(b * Tn + c * Ln) * D4n + d4;
#pragma unroll 8
    for (int j = 0; j < Ln; j++) {
        float4 xv = xp[(size_t)j * D4n];
        float xr[4] = {xv.x, xv.y, xv.z, xv.w};
#pragma unroll
        for (int k = 0; k < 4; k++) {
            float nre = fmaf(rre[k], zre[k], fmaf(-rim[k], zim[k], xr[k]));
            float nim = fmaf(rre[k], zim[k], rim[k] * zre[k]);
            zre[k] = nre;
            zim[k] = nim;
        }
        yp[(size_t)j * D4n] = make_float4(zre[0], zre[1], zre[2], zre[3]);
    }
}

// ---------------------------------------------------------------------------
extern "C" void kernel_launch(void* const* d_in, const int* in_sizes, int n_in,
                              void* d_out, int out_size)
{
    const float* x     = (const float*)d_in[0];
    const float* decay = (const float*)d_in[1];
    const float* freq  = (const float*)d_in[2];
    float* y = (float*)d_out;

    const int n1 = Cn * Bn * D4n;      // 262144 threads
    const int n2 = Bn * 4 * D4n;       // 4096 threads

    k_setup<<<(Dn + 255) / 256, 256>>>(decay, freq);
    k_pass1<<<n1 / 256, 256>>>((const float4*)x);
    k_pass2<<<(n2 + 255) / 256, 256>>>(decay, freq);
    k_pass3<<<n1 / 256, 256>>>((const float4*)x, (float4*)y);
}